// round 8
// baseline (speedup 1.0000x reference)
#include <cuda_runtime.h>
#include <math.h>
#include <stdint.h>

#define BATCH 8
#define SEQ   256
#define F0    512
#define F1    256
#define F2    128
#define KMAX  30
#define NSEG  32      // scanP segments (8 rows each)
#define SMB   16      // softmax blocks per batch
#define TRI_N 32896   // sum_{n=0}^{255} (256-n)

// ---- scratch (__device__ globals; no allocations allowed) ----
__device__ float g_h[BATCH*SEQ*F1];
__device__ float g_z[BATCH*SEQ*F2];
__device__ float g_corr[BATCH*SEQ*SEQ];
__device__ float g_P[BATCH*SEQ*SEQ];
__device__ float g_Pt[BATCH*SEQ*SEQ];      // transpose of P
__device__ float g_Pdiag[BATCH][SEQ];      // P[i][i]
__device__ float g_diag[BATCH][SEQ];       // diag of corr
__device__ float g_seg[BATCH][NSEG][SEQ];
__device__ int   g_ctrS[BATCH];            // epoch counters (never reset)
__device__ float g_C[KMAX][BATCH][SEQ];    // DP C-vectors
__device__ float g_part[BATCH][SMB][SEQ];

// ---- packed fp32x2 helpers (FFMA2) ----
__device__ __forceinline__ void ffma2(unsigned long long& d,
                                      unsigned long long a,
                                      unsigned long long b) {
    asm("fma.rn.f32x2 %0, %1, %2, %0;" : "+l"(d) : "l"(a), "l"(b));
}
__device__ __forceinline__ void unpack2(unsigned long long v, float& lo, float& hi) {
    asm("mov.b64 {%0,%1}, %2;" : "=f"(lo), "=f"(hi) : "l"(v));
}

// epoch cross-block barrier: tid0 only, bracketed by __syncthreads()
__device__ __forceinline__ void gbar(int* ctr, int nblk) {
    __threadfence();
    int old = atomicAdd(ctr, 1);
    int target = (old / nblk + 1) * nblk;
    volatile int* p = ctr;
    while (*p < target) { }
    __threadfence();
}

// ============================================================
// GEMM: C[M,N] = (A[M,K] @ B[K,N]) + bias, optional relu. FFMA2.
// ============================================================
template<int RELU>
__global__ __launch_bounds__(256) void gemm_kernel(
    const float* __restrict__ A, const float* __restrict__ B,
    const float* __restrict__ bias, float* __restrict__ C,
    int M, int N, int K)
{
    __shared__ float As2[16][128];
    __shared__ float Bs[16][64];
    const int m0 = blockIdx.y * 64, n0 = blockIdx.x * 64;
    const int tid = threadIdx.x;
    const int ty = tid >> 4, tx = tid & 15;
    const int arow = tid >> 2, akq = tid & 3;
    const int bkr  = tid >> 4, bnq = tid & 15;

    unsigned long long acc2[4][2] = {};

    for (int k0 = 0; k0 < K; k0 += 16) {
        float4 va = *(const float4*)(A + (size_t)(m0 + arow) * K + k0 + akq * 4);
        *(float2*)&As2[akq*4+0][2*arow] = make_float2(va.x, va.x);
        *(float2*)&As2[akq*4+1][2*arow] = make_float2(va.y, va.y);
        *(float2*)&As2[akq*4+2][2*arow] = make_float2(va.z, va.z);
        *(float2*)&As2[akq*4+3][2*arow] = make_float2(va.w, va.w);
        float4 vb = *(const float4*)(B + (size_t)(k0 + bkr) * N + n0 + bnq * 4);
        *(float4*)&Bs[bkr][bnq*4] = vb;
        __syncthreads();
        #pragma unroll
        for (int k = 0; k < 16; k++) {
            ulonglong2 a01 = *(const ulonglong2*)&As2[k][ty*8];
            ulonglong2 a23 = *(const ulonglong2*)&As2[k][ty*8 + 4];
            ulonglong2 bq  = *(const ulonglong2*)&Bs[k][tx*4];
            ffma2(acc2[0][0], a01.x, bq.x); ffma2(acc2[0][1], a01.x, bq.y);
            ffma2(acc2[1][0], a01.y, bq.x); ffma2(acc2[1][1], a01.y, bq.y);
            ffma2(acc2[2][0], a23.x, bq.x); ffma2(acc2[2][1], a23.x, bq.y);
            ffma2(acc2[3][0], a23.y, bq.x); ffma2(acc2[3][1], a23.y, bq.y);
        }
        __syncthreads();
    }

    #pragma unroll
    for (int r = 0; r < 4; r++) {
        int m = m0 + ty*4 + r;
        #pragma unroll
        for (int c2 = 0; c2 < 2; c2++) {
            float v0, v1;
            unpack2(acc2[r][c2], v0, v1);
            int n = n0 + tx*4 + c2*2;
            v0 += bias[n]; v1 += bias[n+1];
            if (RELU) { v0 = fmaxf(v0, 0.0f); v1 = fmaxf(v1, 0.0f); }
            *(float2*)(C + (size_t)m * N + n) = make_float2(v0, v1);
        }
    }
}

// ============================================================
// corr[b] = z_b @ z_b^T (NT) via FFMA2 + diag capture.
// ============================================================
__global__ __launch_bounds__(256) void syrk_kernel()
{
    __shared__ float As2[16][128];
    __shared__ float Bs[16][64];
    const int bz = blockIdx.z;
    const float* Z = g_z + (size_t)bz * SEQ * F2;
    float* C = g_corr + (size_t)bz * SEQ * SEQ;
    const int m0 = blockIdx.y * 64, n0 = blockIdx.x * 64;
    const int tid = threadIdx.x;
    const int ty = tid >> 4, tx = tid & 15;
    const int row = tid >> 2, kq = tid & 3;

    unsigned long long acc2[4][2] = {};

    for (int k0 = 0; k0 < F2; k0 += 16) {
        float4 va = *(const float4*)(Z + (size_t)(m0 + row) * F2 + k0 + kq * 4);
        *(float2*)&As2[kq*4+0][2*row] = make_float2(va.x, va.x);
        *(float2*)&As2[kq*4+1][2*row] = make_float2(va.y, va.y);
        *(float2*)&As2[kq*4+2][2*row] = make_float2(va.z, va.z);
        *(float2*)&As2[kq*4+3][2*row] = make_float2(va.w, va.w);
        float4 vb = *(const float4*)(Z + (size_t)(n0 + row) * F2 + k0 + kq * 4);
        Bs[kq*4+0][row] = vb.x; Bs[kq*4+1][row] = vb.y;
        Bs[kq*4+2][row] = vb.z; Bs[kq*4+3][row] = vb.w;
        __syncthreads();
        #pragma unroll
        for (int k = 0; k < 16; k++) {
            ulonglong2 a01 = *(const ulonglong2*)&As2[k][ty*8];
            ulonglong2 a23 = *(const ulonglong2*)&As2[k][ty*8 + 4];
            ulonglong2 bq  = *(const ulonglong2*)&Bs[k][tx*4];
            ffma2(acc2[0][0], a01.x, bq.x); ffma2(acc2[0][1], a01.x, bq.y);
            ffma2(acc2[1][0], a01.y, bq.x); ffma2(acc2[1][1], a01.y, bq.y);
            ffma2(acc2[2][0], a23.x, bq.x); ffma2(acc2[2][1], a23.x, bq.y);
            ffma2(acc2[3][0], a23.y, bq.x); ffma2(acc2[3][1], a23.y, bq.y);
        }
        __syncthreads();
    }

    #pragma unroll
    for (int r = 0; r < 4; r++) {
        int m = m0 + ty*4 + r;
        #pragma unroll
        for (int c2 = 0; c2 < 2; c2++) {
            float v0, v1;
            unpack2(acc2[r][c2], v0, v1);
            int n = n0 + tx*4 + c2*2;
            C[(size_t)m * SEQ + n]     = v0;
            C[(size_t)m * SEQ + n + 1] = v1;
            if (m == n)     g_diag[bz][m] = v0;
            if (m == n + 1) g_diag[bz][m] = v1;
        }
    }
}

// ============================================================
// scanP: fused D + row-scan + col-scan -> P, Pt, Pdiag.
// Block = (segment s of 8 rows, batch b), 256 threads.
// ============================================================
__global__ __launch_bounds__(256) void scanP_kernel()
{
    __shared__ float T[8][SEQ];
    __shared__ float off[SEQ];
    __shared__ float sdn[8];
    const int s = blockIdx.x, b = blockIdx.y;
    const int tid = threadIdx.x;
    const int n0 = s * 8;
    const float* cb = g_corr + (size_t)b * SEQ * SEQ;

    if (tid < 8) sdn[tid] = g_diag[b][n0 + tid];
    const float di = g_diag[b][tid];
    __syncthreads();

    float run = 0.0f;
    #pragma unroll
    for (int n = 0; n < 8; n++) {
        float denom = sqrtf(fmaxf(sdn[n] * di, 1e-8f));
        float d = (1.0f - cb[(size_t)(n0 + n) * SEQ + tid] / denom) * 0.5f;
        run += d;
        T[n][tid] = run;
    }
    g_seg[b][s][tid] = run;
    __syncthreads();
    if (tid == 0) gbar(&g_ctrS[b], NSEG);
    __syncthreads();

    float o = 0.0f;
    for (int sp = 0; sp < s; sp++) o += __ldcg(&g_seg[b][sp][tid]);
    off[tid] = o;
    __syncthreads();

    const int w = tid >> 5, l = tid & 31;
    const int row = n0 + w;
    float v[8];
    #pragma unroll
    for (int j = 0; j < 8; j++) v[j] = T[w][l*8 + j] + off[l*8 + j];
    #pragma unroll
    for (int j = 1; j < 8; j++) v[j] += v[j-1];
    float tot = v[7], inc = tot;
    #pragma unroll
    for (int d2 = 1; d2 < 32; d2 <<= 1) {
        float t2 = __shfl_up_sync(0xffffffffu, inc, d2);
        if (l >= d2) inc += t2;
    }
    float excl = inc - tot;
    #pragma unroll
    for (int j = 0; j < 8; j++) v[j] += excl;

    float* P = g_P + ((size_t)b * SEQ + row) * SEQ;
    *(float4*)(P + l*8)     = make_float4(v[0], v[1], v[2], v[3]);
    *(float4*)(P + l*8 + 4) = make_float4(v[4], v[5], v[6], v[7]);
    // transpose + diag
    float* Pt = g_Pt + (size_t)b * SEQ * SEQ;
    #pragma unroll
    for (int j = 0; j < 8; j++) {
        int i = l*8 + j;
        Pt[(size_t)i * SEQ + row] = v[j];
        if (i == row) g_Pdiag[b][row] = v[j];
    }
}

// ============================================================
// minDP: one block per batch, 1024 threads. Ds upper triangle
// built from P/Pt/Pdiag into smem (132KB); 29 min-plus steps,
// only __syncthreads between steps. C table streamed to gmem.
// ============================================================
__global__ __launch_bounds__(1024) void minDP_kernel()
{
    extern __shared__ float sm[];
    float* tri = sm;                 // TRI_N floats
    float* sCa = sm + TRI_N;         // 258
    float* sCb = sCa + 258;          // 258
    const int b = blockIdx.x;
    const int tid = threadIdx.x, w = tid >> 5, l = tid & 31;
    const float* P  = g_P  + (size_t)b * SEQ * SEQ;
    const float* Pt = g_Pt + (size_t)b * SEQ * SEQ;

    if (tid < 2) { sCa[SEQ + tid] = 0.0f; sCb[SEQ + tid] = 0.0f; }

    // ---- build Ds upper triangle (warp w owns rows w+32m) ----
    int on[8];
    #pragma unroll
    for (int m = 0; m < 8; m++) {
        const int n = w + 32*m;
        on[m] = n*SEQ - (n*(n-1))/2;
        const float pd = (n == 0) ? 0.0f : g_Pdiag[b][n-1];
        const float* Prow  = P  + (size_t)(n-1) * SEQ;
        const float* Ptrow = Pt + (size_t)(n-1) * SEQ;
        const int jn = (SEQ - n + 31) >> 5;
        for (int j = 0; j < jn; j++) {
            int i = n + l + 32*j;
            if (i < SEQ) {
                float a  = g_Pdiag[b][i];
                float bb = (n == 0) ? 0.0f : Prow[i];
                float cc = (n == 0) ? 0.0f : Ptrow[i];
                float val = ((a - bb) - cc) + pd;
                tri[on[m] + l + 32*j] = val;
                if (i == SEQ - 1) { sCa[n] = val; g_C[0][b][n] = val; }
            }
        }
    }
    __syncthreads();

    // ---- 29 min-plus steps, smem only ----
    float* cur = sCa;
    float* nxt = sCb;
    #pragma unroll 1
    for (int kk = 1; kk < KMAX; kk++) {
        const int limit = SEQ - kk;
        #pragma unroll
        for (int m = 0; m < 8; m++) {
            const int n = w + 32*m;
            if (n < limit) {
                float mn = 3.0e38f;
                const float* trow = tri + on[m];
                const float* crow = cur + n + 1;
                const int jn = (limit - n + 31) >> 5;
                for (int j = 0; j < jn; j++) {
                    int q = l + 32*j;
                    float t = (n + q < limit) ? (trow[q] + crow[q]) : 3.0e38f;
                    mn = fminf(mn, t);
                }
                #pragma unroll
                for (int o = 16; o > 0; o >>= 1)
                    mn = fminf(mn, __shfl_xor_sync(0xffffffffu, mn, o));
                if (l == 0) { nxt[n] = mn; __stcg(&g_C[kk][b][n], mn); }
            }
        }
        __syncthreads();
        float* tmp = cur; cur = nxt; nxt = tmp;
    }
}

// ============================================================
// softmax: wide (BATCH x SMB blocks, 512 thr). Stages C table,
// rebuilds its 2 rows/warp from P/Pt/Pdiag, accumulates.
// ============================================================
__global__ __launch_bounds__(512) void softmax_kernel()
{
    __shared__ float sC[KMAX][SEQ + 2];     // ~31KB
    __shared__ float s_acc[16][SEQ];        // 16KB
    const int b = blockIdx.x, blk = blockIdx.y;
    const int tid = threadIdx.x, w = tid >> 5, l = tid & 31;
    const float* P  = g_P  + (size_t)b * SEQ * SEQ;
    const float* Pt = g_Pt + (size_t)b * SEQ * SEQ;

    for (int idx = tid; idx < KMAX*SEQ; idx += 512)
        sC[idx >> 8][idx & 255] = g_C[idx >> 8][b][idx & 255];
    if (tid < 2*KMAX) sC[tid >> 1][SEQ + (tid & 1)] = 0.0f;

    // build 2 rows (wb0, wb0+1) from P (all coalesced)
    const int wb0 = blk * 32 + 2*w;
    float rowv[2][8];
    #pragma unroll
    for (int rr = 0; rr < 2; rr++) {
        const int wb = wb0 + rr;
        const float pd = (wb == 0) ? 0.0f : g_Pdiag[b][wb-1];
        const float* Prow  = P  + (size_t)(wb-1) * SEQ;
        const float* Ptrow = Pt + (size_t)(wb-1) * SEQ;
        #pragma unroll
        for (int j = 0; j < 8; j++) {
            int i = l + 32*j;
            if (i >= wb) {
                float a  = g_Pdiag[b][i];
                float bb = (wb == 0) ? 0.0f : Prow[i];
                float cc = (wb == 0) ? 0.0f : Ptrow[i];
                rowv[rr][j] = ((a - bb) - cc) + pd;
            } else {
                rowv[rr][j] = 3.0e38f;
            }
        }
    }
    __syncthreads();

    float acc[8] = {};
    #pragma unroll 1
    for (int rr = 0; rr < 2; rr++) {
        const int wb = wb0 + rr;
        #pragma unroll 1
        for (int kk = 1; kk < KMAX; kk++) {
            const int limit = SEQ - kk;
            if (wb >= limit) break;
            const float mn = sC[kk][wb];
            float e[8];
            float s = 0.0f;
            #pragma unroll
            for (int j = 0; j < 8; j++) {
                e[j] = 0.0f;
                if (32*j + 31 >= wb && 32*j < limit) {      // warp-uniform skip
                    int i = l + 32*j;
                    float t = (i < limit) ? (rowv[rr][j] + sC[kk-1][i + 1]) : 3.0e38f;
                    e[j] = __expf(mn - t);
                    s += e[j];
                }
            }
            #pragma unroll
            for (int o = 16; o > 0; o >>= 1)
                s += __shfl_xor_sync(0xffffffffu, s, o);
            float inv = __fdividef(1.0f, s);
            #pragma unroll
            for (int j = 0; j < 8; j++) acc[j] += e[j] * inv;
        }
    }

    #pragma unroll
    for (int j = 0; j < 8; j++) s_acc[w][l + 32*j] = acc[j];
    __syncthreads();
    if (tid < SEQ) {
        float sum = 0.0f;
        #pragma unroll
        for (int ww = 0; ww < 16; ww++) sum += s_acc[ww][tid];
        g_part[b][blk][tid] = sum;
    }
}

// out[b][i] = (sum of partials + k0 term) / exact mask count
__global__ __launch_bounds__(256) void finalize_kernel(float* __restrict__ out)
{
    const int b = blockIdx.x, i = threadIdx.x;
    float num = (i == SEQ - 1) ? (float)SEQ : 0.0f;
    #pragma unroll
    for (int p = 0; p < SMB; p++) num += g_part[b][p][i];
    int m = min(KMAX - 1, SEQ - 1 - i);
    float cnt = (float)((i + 1) * m + ((i == SEQ - 1) ? SEQ : 0));
    out[b*SEQ + i] = num / cnt;
}

// ============================================================
extern "C" void kernel_launch(void* const* d_in, const int* in_sizes, int n_in,
                              void* d_out, int out_size)
{
    const float* x  = (const float*)d_in[0];
    const float* W0 = (const float*)d_in[1];
    const float* b0 = (const float*)d_in[2];
    const float* W1 = (const float*)d_in[3];
    const float* b1 = (const float*)d_in[4];
    float* out = (float*)d_out;

    static float* p_h = nullptr;
    static float* p_z = nullptr;
    static const int MINDP_SMEM = (TRI_N + 2*258) * 4;
    if (!p_h) {
        cudaGetSymbolAddress((void**)&p_h, g_h);
        cudaGetSymbolAddress((void**)&p_z, g_z);
        cudaFuncSetAttribute(minDP_kernel,
                             cudaFuncAttributeMaxDynamicSharedMemorySize, MINDP_SMEM);
    }

    gemm_kernel<1><<<dim3(F1/64, (BATCH*SEQ)/64), 256>>>(x,   W0, b0, p_h, BATCH*SEQ, F1, F0);
    gemm_kernel<0><<<dim3(F2/64, (BATCH*SEQ)/64), 256>>>(p_h, W1, b1, p_z, BATCH*SEQ, F2, F1);
    syrk_kernel    <<<dim3(SEQ/64, SEQ/64, BATCH), 256>>>();
    scanP_kernel   <<<dim3(NSEG, BATCH), 256>>>();
    minDP_kernel   <<<BATCH, 1024, MINDP_SMEM>>>();
    softmax_kernel <<<dim3(BATCH, SMB), 512>>>();
    finalize_kernel<<<BATCH, SEQ>>>(out);
}

// round 9
// speedup vs baseline: 1.3239x; 1.3239x over previous
#include <cuda_runtime.h>
#include <math.h>
#include <stdint.h>

#define BATCH 8
#define SEQ   256
#define F0    512
#define F1    256
#define F2    128
#define KMAX  30
#define NSEG  32      // scanP segments (8 rows each)
#define DPB   8       // dp blocks per batch (32 rows each, 1 row/warp)

// ---- scratch (__device__ globals; no allocations allowed) ----
__device__ float g_h[BATCH*SEQ*F1];
__device__ float g_z[BATCH*SEQ*F2];
__device__ float g_corr[BATCH*SEQ*SEQ];
__device__ float g_P[BATCH*SEQ*SEQ];
__device__ float g_Pt[BATCH*SEQ*SEQ];      // transpose of P
__device__ float g_Pdiag[BATCH][SEQ];      // P[i][i]
__device__ float g_diag[BATCH][SEQ];       // diag of corr
__device__ float g_seg[BATCH][NSEG][SEQ];
__device__ int   g_ctrS[BATCH];            // scanP epoch counters (never reset)
__device__ float g_Cc[KMAX][BATCH][SEQ];   // DP C-vectors (published chunks)
__device__ int   g_flag[BATCH][KMAX][DPB]; // per-(step,chunk) ready flags (reset each replay)
__device__ float g_part[BATCH][DPB][SEQ];  // per-block partial numerators

// dpsm dynamic smem layout
#define SCROW 260
#define ACC_OFF (KMAX*SCROW)                       // floats
#define DSM_FLOATS (KMAX*SCROW + 32*SEQ)
#define DSM_BYTES  (DSM_FLOATS*4)

// ---- packed fp32x2 helpers (FFMA2) ----
__device__ __forceinline__ void ffma2(unsigned long long& d,
                                      unsigned long long a,
                                      unsigned long long b) {
    asm("fma.rn.f32x2 %0, %1, %2, %0;" : "+l"(d) : "l"(a), "l"(b));
}
__device__ __forceinline__ void unpack2(unsigned long long v, float& lo, float& hi) {
    asm("mov.b64 {%0,%1}, %2;" : "=f"(lo), "=f"(hi) : "l"(v));
}

// epoch cross-block barrier (scanP only)
__device__ __forceinline__ void gbar(int* ctr, int nblk) {
    __threadfence();
    int old = atomicAdd(ctr, 1);
    int target = (old / nblk + 1) * nblk;
    volatile int* p = ctr;
    while (*p < target) { }
    __threadfence();
}

// ============================================================
// GEMM: C[M,N] = (A[M,K] @ B[K,N]) + bias, optional relu. FFMA2.
// ============================================================
template<int RELU>
__global__ __launch_bounds__(256) void gemm_kernel(
    const float* __restrict__ A, const float* __restrict__ B,
    const float* __restrict__ bias, float* __restrict__ C,
    int M, int N, int K)
{
    __shared__ float As2[16][128];
    __shared__ float Bs[16][64];
    const int m0 = blockIdx.y * 64, n0 = blockIdx.x * 64;
    const int tid = threadIdx.x;
    const int ty = tid >> 4, tx = tid & 15;
    const int arow = tid >> 2, akq = tid & 3;
    const int bkr  = tid >> 4, bnq = tid & 15;

    unsigned long long acc2[4][2] = {};

    for (int k0 = 0; k0 < K; k0 += 16) {
        float4 va = *(const float4*)(A + (size_t)(m0 + arow) * K + k0 + akq * 4);
        *(float2*)&As2[akq*4+0][2*arow] = make_float2(va.x, va.x);
        *(float2*)&As2[akq*4+1][2*arow] = make_float2(va.y, va.y);
        *(float2*)&As2[akq*4+2][2*arow] = make_float2(va.z, va.z);
        *(float2*)&As2[akq*4+3][2*arow] = make_float2(va.w, va.w);
        float4 vb = *(const float4*)(B + (size_t)(k0 + bkr) * N + n0 + bnq * 4);
        *(float4*)&Bs[bkr][bnq*4] = vb;
        __syncthreads();
        #pragma unroll
        for (int k = 0; k < 16; k++) {
            ulonglong2 a01 = *(const ulonglong2*)&As2[k][ty*8];
            ulonglong2 a23 = *(const ulonglong2*)&As2[k][ty*8 + 4];
            ulonglong2 bq  = *(const ulonglong2*)&Bs[k][tx*4];
            ffma2(acc2[0][0], a01.x, bq.x); ffma2(acc2[0][1], a01.x, bq.y);
            ffma2(acc2[1][0], a01.y, bq.x); ffma2(acc2[1][1], a01.y, bq.y);
            ffma2(acc2[2][0], a23.x, bq.x); ffma2(acc2[2][1], a23.x, bq.y);
            ffma2(acc2[3][0], a23.y, bq.x); ffma2(acc2[3][1], a23.y, bq.y);
        }
        __syncthreads();
    }

    #pragma unroll
    for (int r = 0; r < 4; r++) {
        int m = m0 + ty*4 + r;
        #pragma unroll
        for (int c2 = 0; c2 < 2; c2++) {
            float v0, v1;
            unpack2(acc2[r][c2], v0, v1);
            int n = n0 + tx*4 + c2*2;
            v0 += bias[n]; v1 += bias[n+1];
            if (RELU) { v0 = fmaxf(v0, 0.0f); v1 = fmaxf(v1, 0.0f); }
            *(float2*)(C + (size_t)m * N + n) = make_float2(v0, v1);
        }
    }
}

// ============================================================
// corr[b] = z_b @ z_b^T (NT) via FFMA2 + diag capture.
// Block (0,0,0) also zeroes the dp pipeline flags for this replay
// (runs strictly before dpsm in the stream).
// ============================================================
__global__ __launch_bounds__(256) void syrk_kernel()
{
    __shared__ float As2[16][128];
    __shared__ float Bs[16][64];
    const int bz = blockIdx.z;
    const float* Z = g_z + (size_t)bz * SEQ * F2;
    float* C = g_corr + (size_t)bz * SEQ * SEQ;
    const int m0 = blockIdx.y * 64, n0 = blockIdx.x * 64;
    const int tid = threadIdx.x;
    const int ty = tid >> 4, tx = tid & 15;
    const int row = tid >> 2, kq = tid & 3;

    if (blockIdx.x == 0 && blockIdx.y == 0 && bz == 0) {
        for (int i = tid; i < BATCH*KMAX*DPB; i += 256)
            ((int*)g_flag)[i] = 0;
    }

    unsigned long long acc2[4][2] = {};

    for (int k0 = 0; k0 < F2; k0 += 16) {
        float4 va = *(const float4*)(Z + (size_t)(m0 + row) * F2 + k0 + kq * 4);
        *(float2*)&As2[kq*4+0][2*row] = make_float2(va.x, va.x);
        *(float2*)&As2[kq*4+1][2*row] = make_float2(va.y, va.y);
        *(float2*)&As2[kq*4+2][2*row] = make_float2(va.z, va.z);
        *(float2*)&As2[kq*4+3][2*row] = make_float2(va.w, va.w);
        float4 vb = *(const float4*)(Z + (size_t)(n0 + row) * F2 + k0 + kq * 4);
        Bs[kq*4+0][row] = vb.x; Bs[kq*4+1][row] = vb.y;
        Bs[kq*4+2][row] = vb.z; Bs[kq*4+3][row] = vb.w;
        __syncthreads();
        #pragma unroll
        for (int k = 0; k < 16; k++) {
            ulonglong2 a01 = *(const ulonglong2*)&As2[k][ty*8];
            ulonglong2 a23 = *(const ulonglong2*)&As2[k][ty*8 + 4];
            ulonglong2 bq  = *(const ulonglong2*)&Bs[k][tx*4];
            ffma2(acc2[0][0], a01.x, bq.x); ffma2(acc2[0][1], a01.x, bq.y);
            ffma2(acc2[1][0], a01.y, bq.x); ffma2(acc2[1][1], a01.y, bq.y);
            ffma2(acc2[2][0], a23.x, bq.x); ffma2(acc2[2][1], a23.x, bq.y);
            ffma2(acc2[3][0], a23.y, bq.x); ffma2(acc2[3][1], a23.y, bq.y);
        }
        __syncthreads();
    }

    #pragma unroll
    for (int r = 0; r < 4; r++) {
        int m = m0 + ty*4 + r;
        #pragma unroll
        for (int c2 = 0; c2 < 2; c2++) {
            float v0, v1;
            unpack2(acc2[r][c2], v0, v1);
            int n = n0 + tx*4 + c2*2;
            C[(size_t)m * SEQ + n]     = v0;
            C[(size_t)m * SEQ + n + 1] = v1;
            if (m == n)     g_diag[bz][m] = v0;
            if (m == n + 1) g_diag[bz][m] = v1;
        }
    }
}

// ============================================================
// scanP: fused D + row-scan + col-scan -> P, Pt, Pdiag.
// ============================================================
__global__ __launch_bounds__(256) void scanP_kernel()
{
    __shared__ float T[8][SEQ];
    __shared__ float off[SEQ];
    __shared__ float sdn[8];
    const int s = blockIdx.x, b = blockIdx.y;
    const int tid = threadIdx.x;
    const int n0 = s * 8;
    const float* cb = g_corr + (size_t)b * SEQ * SEQ;

    if (tid < 8) sdn[tid] = g_diag[b][n0 + tid];
    const float di = g_diag[b][tid];
    __syncthreads();

    float run = 0.0f;
    #pragma unroll
    for (int n = 0; n < 8; n++) {
        float denom = sqrtf(fmaxf(sdn[n] * di, 1e-8f));
        float d = (1.0f - cb[(size_t)(n0 + n) * SEQ + tid] / denom) * 0.5f;
        run += d;
        T[n][tid] = run;
    }
    g_seg[b][s][tid] = run;
    __syncthreads();
    if (tid == 0) gbar(&g_ctrS[b], NSEG);
    __syncthreads();

    float o = 0.0f;
    for (int sp = 0; sp < s; sp++) o += __ldcg(&g_seg[b][sp][tid]);
    off[tid] = o;
    __syncthreads();

    const int w = tid >> 5, l = tid & 31;
    const int row = n0 + w;
    float v[8];
    #pragma unroll
    for (int j = 0; j < 8; j++) v[j] = T[w][l*8 + j] + off[l*8 + j];
    #pragma unroll
    for (int j = 1; j < 8; j++) v[j] += v[j-1];
    float tot = v[7], inc = tot;
    #pragma unroll
    for (int d2 = 1; d2 < 32; d2 <<= 1) {
        float t2 = __shfl_up_sync(0xffffffffu, inc, d2);
        if (l >= d2) inc += t2;
    }
    float excl = inc - tot;
    #pragma unroll
    for (int j = 0; j < 8; j++) v[j] += excl;

    float* P = g_P + ((size_t)b * SEQ + row) * SEQ;
    *(float4*)(P + l*8)     = make_float4(v[0], v[1], v[2], v[3]);
    *(float4*)(P + l*8 + 4) = make_float4(v[4], v[5], v[6], v[7]);
    float* Pt = g_Pt + (size_t)b * SEQ * SEQ;
    #pragma unroll
    for (int j = 0; j < 8; j++) {
        int i = l*8 + j;
        Pt[(size_t)i * SEQ + row] = v[j];
        if (i == row) g_Pdiag[b][row] = v[j];
    }
}

// ============================================================
// dpsm: pipelined DP + fused softmax. Grid (BATCH, DPB), 1024 thr.
// Block g owns rows [32g, 32g+32), 1 row/warp (8 regs). Per step,
// block g needs only chunks g..7 of C_prev: own chunk is local,
// higher chunks are read from L2 once their (step,chunk) flag is
// set. Producers (high g) run ahead -> consumers rarely stall.
// ============================================================
__global__ __launch_bounds__(1024) void dpsm_kernel()
{
    extern __shared__ float sm[];
    float (*sC)[SCROW]  = (float(*)[SCROW])sm;          // C table (persists)
    float (*sacc)[SEQ]  = (float(*)[SEQ])(sm + ACC_OFF); // warp accumulators
    const int b = blockIdx.x, g = blockIdx.y;
    const int tid = threadIdx.x, w = tid >> 5, l = tid & 31;
    const int wb = g * 32 + w;                  // this warp's row
    const float* P  = g_P  + (size_t)b * SEQ * SEQ;
    const float* Pt = g_Pt + (size_t)b * SEQ * SEQ;

    // ---- build Ds row wb from 4-corner formula (all coalesced) ----
    float rowv[8];
    {
        const float pd = (wb == 0) ? 0.0f : g_Pdiag[b][wb-1];
        const float* Prow  = P  + (size_t)(wb-1) * SEQ;
        const float* Ptrow = Pt + (size_t)(wb-1) * SEQ;
        #pragma unroll
        for (int j = 0; j < 8; j++) {
            int i = l + 32*j;
            if (i >= wb) {
                float a  = g_Pdiag[b][i];
                float bb = (wb == 0) ? 0.0f : Prow[i];
                float cc = (wb == 0) ? 0.0f : Ptrow[i];
                rowv[j] = ((a - bb) - cc) + pd;
            } else {
                rowv[j] = 3.0e38f;
            }
        }
    }

    // ---- publish own chunk of C0 = Ds[.,255] ----
    if (l == 31) { sC[0][wb] = rowv[7]; __stcg(&g_Cc[0][b][wb], rowv[7]); }
    __syncthreads();
    if (tid == 0) { __threadfence(); *(volatile int*)&g_flag[b][0][g] = 1; }

    // ---- pipelined DP: 29 steps ----
    #pragma unroll 1
    for (int kk = 1; kk < KMAX; kk++) {
        // wait for foreign chunks of C_{kk-1} (usually already set)
        if (w == 0) {
            if (l < DPB && l > g) {
                volatile int* f = &g_flag[b][kk-1][l];
                while (*f == 0) { }
            }
            __syncwarp();
            if (l == 0) __threadfence();        // acquire
        }
        __syncthreads();
        // stage foreign part of C_{kk-1} into smem
        if (tid >= (g + 1) * 32 && tid < SEQ)
            sC[kk-1][tid] = __ldcg(&g_Cc[kk-1][b][tid]);
        __syncthreads();

        const int limit = SEQ - kk;
        float val = 0.0f;
        if (wb < limit) {
            float mn = 3.0e38f;
            #pragma unroll
            for (int j = 0; j < 8; j++) {
                int i = l + 32*j;
                float t = (i < limit) ? (rowv[j] + sC[kk-1][i + 1]) : 3.0e38f;
                mn = fminf(mn, t);
            }
            #pragma unroll
            for (int o = 16; o > 0; o >>= 1)
                mn = fminf(mn, __shfl_xor_sync(0xffffffffu, mn, o));
            val = mn;
        }
        if (l == 0) { sC[kk][wb] = val; __stcg(&g_Cc[kk][b][wb], val); }
        __syncthreads();
        if (tid == 0) { __threadfence(); *(volatile int*)&g_flag[b][kk][g] = 1; }
    }
    __syncthreads();

    // ---- barrier-free softmax accumulation from smem C table ----
    float acc[8] = {};
    #pragma unroll 1
    for (int kk = 1; kk < KMAX; kk++) {
        const int limit = SEQ - kk;
        if (wb >= limit) break;
        const float mn = sC[kk][wb];
        float e[8];
        float s = 0.0f;
        #pragma unroll
        for (int j = 0; j < 8; j++) {
            e[j] = 0.0f;
            if (32*j + 31 >= wb && 32*j < limit) {        // warp-uniform skip
                int i = l + 32*j;
                float t = (i < limit) ? (rowv[j] + sC[kk-1][i + 1]) : 3.0e38f;
                e[j] = __expf(mn - t);                    // i<wb lanes -> 0
                s += e[j];
            }
        }
        #pragma unroll
        for (int o = 16; o > 0; o >>= 1)
            s += __shfl_xor_sync(0xffffffffu, s, o);
        float inv = __fdividef(1.0f, s);
        #pragma unroll
        for (int j = 0; j < 8; j++) acc[j] += e[j] * inv;
    }

    // ---- block reduce -> partials ----
    #pragma unroll
    for (int j = 0; j < 8; j++) sacc[w][l + 32*j] = acc[j];
    __syncthreads();
    if (tid < SEQ) {
        float sum = 0.0f;
        #pragma unroll
        for (int ww = 0; ww < 32; ww++) sum += sacc[ww][tid];
        g_part[b][g][tid] = sum;
    }
}

// out[b][i] = (sum of partials + k0 term) / exact mask count
__global__ __launch_bounds__(256) void finalize_kernel(float* __restrict__ out)
{
    const int b = blockIdx.x, i = threadIdx.x;
    float num = (i == SEQ - 1) ? (float)SEQ : 0.0f;
    #pragma unroll
    for (int p = 0; p < DPB; p++) num += g_part[b][p][i];
    int m = min(KMAX - 1, SEQ - 1 - i);
    float cnt = (float)((i + 1) * m + ((i == SEQ - 1) ? SEQ : 0));
    out[b*SEQ + i] = num / cnt;
}

// ============================================================
extern "C" void kernel_launch(void* const* d_in, const int* in_sizes, int n_in,
                              void* d_out, int out_size)
{
    const float* x  = (const float*)d_in[0];
    const float* W0 = (const float*)d_in[1];
    const float* b0 = (const float*)d_in[2];
    const float* W1 = (const float*)d_in[3];
    const float* b1 = (const float*)d_in[4];
    float* out = (float*)d_out;

    static float* p_h = nullptr;
    static float* p_z = nullptr;
    if (!p_h) {
        cudaGetSymbolAddress((void**)&p_h, g_h);
        cudaGetSymbolAddress((void**)&p_z, g_z);
        cudaFuncSetAttribute(dpsm_kernel,
                             cudaFuncAttributeMaxDynamicSharedMemorySize, DSM_BYTES);
    }

    gemm_kernel<1><<<dim3(F1/64, (BATCH*SEQ)/64), 256>>>(x,   W0, b0, p_h, BATCH*SEQ, F1, F0);
    gemm_kernel<0><<<dim3(F2/64, (BATCH*SEQ)/64), 256>>>(p_h, W1, b1, p_z, BATCH*SEQ, F2, F1);
    syrk_kernel    <<<dim3(SEQ/64, SEQ/64, BATCH), 256>>>();
    scanP_kernel   <<<dim3(NSEG, BATCH), 256>>>();
    dpsm_kernel    <<<dim3(BATCH, DPB), 1024, DSM_BYTES>>>();
    finalize_kernel<<<BATCH, SEQ>>>(out);
}